// round 13
// baseline (speedup 1.0000x reference)
#include <cuda_runtime.h>

#define B_ 64
#define R_ 32
#define N_ 16384
#define D_ 64
#define O_ 8
#define SPLIT_ 32
#define CHUNK_ (N_ / SPLIT_)    /* 512 = 256 threads * 2 n */
#define THREADS_ 256
#define NWARP_ (THREADS_ / 32)

// Plain-store partials: every slot written every launch -> no zeroing pass.
__device__ __align__(16) float g_part[B_][SPLIT_][D_];
__device__ float g_cnt[B_][SPLIT_];
// Completion counters (zero-init .bss; finalizer resets them each launch).
__device__ unsigned g_done[B_];

// ---------------------------------------------------------------------------
// Single launch. grid = (B, 32) = 2048 blocks, block = 256; thread owns 2
// consecutive n (warp = 64 contiguous mask bytes per array -> coalesced,
// sector-aligned). 16384 resident warps maximize loads in flight.
// o_types int2 loaded only for the ~11% of n-pairs with a mask hit.
// Sparse hctx rows gathered WARP-COOPERATIVELY: one coalesced 256B load per
// hit, norm via butterfly reduce, accumulate into per-lane registers.
// Last block per b finalizes its 32 outputs.
// ---------------------------------------------------------------------------
__global__ __launch_bounds__(THREADS_)
void ssfw_fused(const float* __restrict__ l_local,
                const float* __restrict__ hctx,
                const float* __restrict__ lambda_so,
                const int*   __restrict__ center_o,
                const int*   __restrict__ o_types,
                const void*  __restrict__ adj,
                const void*  __restrict__ two,
                float*       __restrict__ out) {
    const int b    = blockIdx.x;
    const int part = blockIdx.y;
    const int tid  = threadIdx.x;
    const int warp = tid >> 5;
    const int lane = tid & 31;

    __shared__ __align__(16) float s_part[NWARP_][D_];
    __shared__ int  sh_bytes;       // 1 if masks are packed bytes (numpy bool)
    __shared__ int  s_cnt;
    __shared__ int  s_last;
    if (tid == 0) { sh_bytes = 0; s_cnt = 0; }

    // ---- round-1 loads issued up front (independent; high MLP) ----
    // probe: first 1KB of each mask array (identical across blocks, L2-hot)
    unsigned pa0 = ((const unsigned*)adj)[tid];
    unsigned pt0 = ((const unsigned*)two)[tid];

    const int n_glob = b * N_ + part * CHUNK_ + tid * 2;   // fits in int (max 1M)

    // speculative byte-view mask loads: 2 bytes per array (2B-aligned)
    unsigned short ba = *(const unsigned short*)((const unsigned char*)adj + n_glob);
    unsigned short bt = *(const unsigned short*)((const unsigned char*)two + n_glob);
    const int ctr = center_o[b];

    // classify: any probe word outside {0, 1, 0x3F800000} => packed bytes
    {
        int isb = 0;
        if (pa0 != 0u && pa0 != 1u && pa0 != 0x3F800000u) isb = 1;
        if (pt0 != 0u && pt0 != 1u && pt0 != 0x3F800000u) isb = 1;
        if (isb) atomicOr(&sh_bytes, 1);
    }
    __syncthreads();

    unsigned m0, m1;
    if (sh_bytes) {
        unsigned u = (unsigned)(ba | bt);
        m0 = u & 0xffu;
        m1 = (u >> 8) & 0xffu;
    } else {
        // word masks: nonzero == true for BOTH int32 0/1 and f32 0.0/1.0
        uint2 va = *(const uint2*)((const int*)adj + n_glob);
        uint2 vt = *(const uint2*)((const int*)two + n_glob);
        m0 = va.x | vt.x;
        m1 = va.y | vt.y;
    }

    // o_types loaded ONLY when this n-pair has a mask hit (~11% of pairs)
    int hb = 0;
    if (m0 | m1) {
        const int2 ov = *(const int2*)(o_types + n_glob);
        if (m0 && ov.x == ctr) hb |= 1;
        if (m1 && ov.y == ctr) hb |= 2;
    }

    // ---- warp-cooperative gather: per-lane register accumulator ----
    // lane owns dims {2*lane, 2*lane+1}
    float accx = 0.0f, accy = 0.0f;
    int   wcnt = 0;
    unsigned hitmask = __ballot_sync(0xffffffffu, hb != 0);
    while (hitmask) {
        int src = __ffs(hitmask) - 1;
        hitmask &= hitmask - 1;
        int shb = __shfl_sync(0xffffffffu, hb, src);
        int snb = __shfl_sync(0xffffffffu, n_glob, src);
        #pragma unroll
        for (int j = 0; j < 2; j++) {
            if ((shb >> j) & 1) {
                wcnt++;
                const float2 v = ((const float2*)(hctx + (long long)(snb + j) * D_))[lane];
                float sq = v.x * v.x + v.y * v.y;
                #pragma unroll
                for (int o = 16; o > 0; o >>= 1)
                    sq += __shfl_xor_sync(0xffffffffu, sq, o);
                float rn = rsqrtf(fmaxf(sq, 1e-12f));
                accx += v.x * rn;
                accy += v.y * rn;
            }
        }
    }
    s_part[warp][lane * 2]     = accx;
    s_part[warp][lane * 2 + 1] = accy;
    if (lane == 0 && wcnt) atomicAdd(&s_cnt, wcnt);
    __syncthreads();

    // ---- reduce 8 warp slices, publish partials ----
    if (tid < D_) {
        float acc = 0.0f;
        #pragma unroll
        for (int w = 0; w < NWARP_; w++) acc += s_part[w][tid];
        g_part[b][part][tid] = acc;
    }
    if (tid == 0) g_cnt[b][part] = (float)s_cnt;

    // ---- last-block-done detection ----
    if (tid == 0) {
        __threadfence();
        unsigned old = atomicAdd(&g_done[b], 1u);
        s_last = (old == SPLIT_ - 1);
    }
    __syncthreads();
    if (!s_last) return;

    // ---- finalize b (this block only) ----
    __shared__ __align__(16) float s_sum[D_];
    __shared__ float s_nv;
    if (tid < D_) {
        float acc = 0.0f;
        #pragma unroll
        for (int p = 0; p < SPLIT_; p++) acc += g_part[b][p][tid];
        s_sum[tid] = acc;
    }
    if (tid == 0) {
        float nv = 0.0f;
        #pragma unroll
        for (int p = 0; p < SPLIT_; p++) nv += g_cnt[b][p];
        s_nv = nv;
        g_done[b] = 0;                  // reset for next graph replay
    }
    __syncthreads();

    const float  nv = s_nv;
    const float2 sv = *(const float2*)(&s_sum[lane * 2]);

    #pragma unroll
    for (int rr = 0; rr < 4; rr++) {    // warp w handles r = w, w+8, w+16, w+24
        const int r = warp + rr * 8;
        const float2* lrow = (const float2*)(l_local + ((long long)b * R_ + r) * D_);
        float2 lv = lrow[lane];

        float sq = lv.x * lv.x + lv.y * lv.y;
        float dp = lv.x * sv.x + lv.y * sv.y;
        #pragma unroll
        for (int o = 16; o > 0; o >>= 1) {
            sq += __shfl_xor_sync(0xffffffffu, sq, o);
            dp += __shfl_xor_sync(0xffffffffu, dp, o);
        }
        if (lane == 0) {
            float rinv = rsqrtf(fmaxf(sq, 1e-12f));
            float avg  = rinv * dp / fmaxf(nv, 1e-9f);
            float lam  = lambda_so[r * O_ + ctr];
            float w    = fmaxf(lam / fmaxf(nv, 1.0f), 0.0f) * (1.0f - avg);
            out[b * R_ + r] = w;
        }
    }
}

// ---------------------------------------------------------------------------
// Launch contract
// Inputs (metadata order): 0 l_local [B,R,D] f32, 1 h_context [B,N,D] f32,
// 2 lambda_so [R,O] f32, 3 center_o [B] i32, 4 o_types [B,N] i32,
// 5 adj_mask [B,N] bool, 6 two_hop_mask [B,N] bool.  Output [B,R] f32.
// ---------------------------------------------------------------------------
extern "C" void kernel_launch(void* const* d_in, const int* in_sizes, int n_in,
                              void* d_out, int out_size) {
    const float* l_local   = (const float*)d_in[0];
    const float* h_context = (const float*)d_in[1];
    const float* lambda_so = (const float*)d_in[2];
    const int*   center_o  = (const int*)d_in[3];
    const int*   o_types   = (const int*)d_in[4];
    const void*  adj_mask  = d_in[5];
    const void*  two_mask  = d_in[6];
    float*       out       = (float*)d_out;

    ssfw_fused<<<dim3(B_, SPLIT_), THREADS_>>>(l_local, h_context, lambda_so,
                                               center_o, o_types,
                                               adj_mask, two_mask, out);
}

// round 15
// speedup vs baseline: 1.3449x; 1.3449x over previous
#include <cuda_runtime.h>

#define B_ 64
#define R_ 32
#define N_ 16384
#define D_ 64
#define O_ 8
#define SPLIT_ 16
#define CHUNK_ (N_ / SPLIT_)    /* 1024 = 256 threads * 4 n */
#define THREADS_ 256
#define NWARP_ (THREADS_ / 32)

// Plain-store partials: every slot written every launch -> no zeroing pass.
__device__ __align__(16) float g_part[B_][SPLIT_][D_];
__device__ float g_cnt[B_][SPLIT_];
// Completion counters (zero-init .bss; finalizer resets them each launch).
__device__ unsigned g_done[B_];

// ---------------------------------------------------------------------------
// Single launch. grid = (B, 16) = 1024 blocks, block = 256; thread owns 4
// consecutive n (warp = 512 contiguous mask bytes per array -> coalesced).
// Masks are WORD-typed (int32 0/1 or float32 0.0/1.0 -- proven by the R14
// byte-path failure + every probe-based pass): nonzero word == true for both.
// o_types int4 loaded only for the ~22% of 4-n groups with a mask hit.
// Sparse hctx rows gathered WARP-COOPERATIVELY: one coalesced 256B load per
// hit, norm via butterfly reduce, accumulate in per-lane registers.
// Last block per b finalizes its 32 outputs.
// ---------------------------------------------------------------------------
__global__ __launch_bounds__(THREADS_)
void ssfw_fused(const float* __restrict__ l_local,
                const float* __restrict__ hctx,
                const float* __restrict__ lambda_so,
                const int*   __restrict__ center_o,
                const int*   __restrict__ o_types,
                const unsigned* __restrict__ adj,
                const unsigned* __restrict__ two,
                float*       __restrict__ out) {
    const int b    = blockIdx.x;
    const int part = blockIdx.y;
    const int tid  = threadIdx.x;
    const int warp = tid >> 5;
    const int lane = tid & 31;

    __shared__ __align__(16) float s_part[NWARP_][D_];
    __shared__ int   s_wcnt[NWARP_];
    __shared__ int   s_last;

    const int n_glob = b * N_ + part * CHUNK_ + tid * 4;   // fits in int (max 1M)

    // word masks: uint4 per array (16B, coalesced across the warp)
    uint4 va = *(const uint4*)(adj + n_glob);
    uint4 vt = *(const uint4*)(two + n_glob);
    const int ctr = center_o[b];

    const unsigned m0 = va.x | vt.x;
    const unsigned m1 = va.y | vt.y;
    const unsigned m2 = va.z | vt.z;
    const unsigned m3 = va.w | vt.w;

    // o_types loaded ONLY when this 4-n group has a mask hit (~22% of groups)
    int hb = 0;
    if (m0 | m1 | m2 | m3) {
        const int4 ov = *(const int4*)(o_types + n_glob);
        if (m0 && ov.x == ctr) hb |= 1;
        if (m1 && ov.y == ctr) hb |= 2;
        if (m2 && ov.z == ctr) hb |= 4;
        if (m3 && ov.w == ctr) hb |= 8;
    }

    // ---- warp-cooperative gather: per-lane register accumulator ----
    // lane owns dims {2*lane, 2*lane+1}
    float accx = 0.0f, accy = 0.0f;
    int   wcnt = 0;                 // warp-uniform
    unsigned hitmask = __ballot_sync(0xffffffffu, hb != 0);
    while (hitmask) {
        int src = __ffs(hitmask) - 1;
        hitmask &= hitmask - 1;
        int shb = __shfl_sync(0xffffffffu, hb, src);
        int snb = __shfl_sync(0xffffffffu, n_glob, src);
        #pragma unroll
        for (int j = 0; j < 4; j++) {
            if ((shb >> j) & 1) {
                wcnt++;
                const float2 v = ((const float2*)(hctx + (long long)(snb + j) * D_))[lane];
                float sq = v.x * v.x + v.y * v.y;
                #pragma unroll
                for (int o = 16; o > 0; o >>= 1)
                    sq += __shfl_xor_sync(0xffffffffu, sq, o);
                float rn = rsqrtf(fmaxf(sq, 1e-12f));
                accx += v.x * rn;
                accy += v.y * rn;
            }
        }
    }
    s_part[warp][lane * 2]     = accx;
    s_part[warp][lane * 2 + 1] = accy;
    if (lane == 0) s_wcnt[warp] = wcnt;
    __syncthreads();

    // ---- reduce 8 warp slices, publish partials ----
    if (tid < D_) {
        float acc = 0.0f;
        #pragma unroll
        for (int w = 0; w < NWARP_; w++) acc += s_part[w][tid];
        g_part[b][part][tid] = acc;
    }
    if (tid == 0) {
        int c = 0;
        #pragma unroll
        for (int w = 0; w < NWARP_; w++) c += s_wcnt[w];
        g_cnt[b][part] = (float)c;
    }

    // ---- last-block-done detection (release atomic orders the stores) ----
    if (tid == 0) {
        unsigned old;
        asm volatile("atom.release.gpu.global.add.u32 %0, [%1], 1;"
                     : "=r"(old) : "l"(&g_done[b]) : "memory");
        s_last = (old == SPLIT_ - 1);
    }
    __syncthreads();
    if (!s_last) return;

    // ---- finalize b (this block only) ----
    __shared__ __align__(16) float s_sum[D_];
    __shared__ float s_nv;
    if (tid < D_) {
        float acc = 0.0f;
        #pragma unroll
        for (int p = 0; p < SPLIT_; p++) acc += g_part[b][p][tid];
        s_sum[tid] = acc;
    }
    if (tid == 0) {
        float nv = 0.0f;
        #pragma unroll
        for (int p = 0; p < SPLIT_; p++) nv += g_cnt[b][p];
        s_nv = nv;
        g_done[b] = 0;                  // reset for next graph replay
    }
    __syncthreads();

    const float  nv = s_nv;
    const float2 sv = *(const float2*)(&s_sum[lane * 2]);

    #pragma unroll
    for (int rr = 0; rr < 4; rr++) {    // warp w handles r = w, w+8, w+16, w+24
        const int r = warp + rr * 8;
        const float2* lrow = (const float2*)(l_local + ((long long)b * R_ + r) * D_);
        float2 lv = lrow[lane];

        float sq = lv.x * lv.x + lv.y * lv.y;
        float dp = lv.x * sv.x + lv.y * sv.y;
        #pragma unroll
        for (int o = 16; o > 0; o >>= 1) {
            sq += __shfl_xor_sync(0xffffffffu, sq, o);
            dp += __shfl_xor_sync(0xffffffffu, dp, o);
        }
        if (lane == 0) {
            float rinv = rsqrtf(fmaxf(sq, 1e-12f));
            float avg  = rinv * dp / fmaxf(nv, 1e-9f);
            float lam  = lambda_so[r * O_ + ctr];
            float w    = fmaxf(lam / fmaxf(nv, 1.0f), 0.0f) * (1.0f - avg);
            out[b * R_ + r] = w;
        }
    }
}

// ---------------------------------------------------------------------------
// Launch contract
// Inputs (metadata order): 0 l_local [B,R,D] f32, 1 h_context [B,N,D] f32,
// 2 lambda_so [R,O] f32, 3 center_o [B] i32, 4 o_types [B,N] i32,
// 5 adj_mask [B,N] (word-typed bool), 6 two_hop_mask [B,N] (word-typed bool).
// Output [B,R] f32.
// ---------------------------------------------------------------------------
extern "C" void kernel_launch(void* const* d_in, const int* in_sizes, int n_in,
                              void* d_out, int out_size) {
    const float* l_local   = (const float*)d_in[0];
    const float* h_context = (const float*)d_in[1];
    const float* lambda_so = (const float*)d_in[2];
    const int*   center_o  = (const int*)d_in[3];
    const int*   o_types   = (const int*)d_in[4];
    const unsigned* adj_mask = (const unsigned*)d_in[5];
    const unsigned* two_mask = (const unsigned*)d_in[6];
    float*       out       = (float*)d_out;

    ssfw_fused<<<dim3(B_, SPLIT_), THREADS_>>>(l_local, h_context, lambda_so,
                                               center_o, o_types,
                                               adj_mask, two_mask, out);
}